// round 2
// baseline (speedup 1.0000x reference)
#include <cuda_runtime.h>

#define NT 1096
#define NS 2048
#define NH 16

__global__ __launch_bounds__(128, 8)
void waternet_kernel(const float* __restrict__ P, const float* __restrict__ T,
                     const float* __restrict__ w_i, const float* __restrict__ w_o,
                     const float* __restrict__ w_l, const float* __restrict__ w_s,
                     float* __restrict__ Q, float* __restrict__ H, float* __restrict__ S)
{
    const int gid  = blockIdx.x * blockDim.x + threadIdx.x;   // site*NH + h
    if (gid >= NS * NH) return;
    const int site = gid >> 4;
    const int hidx = gid & 15;

    // Time-invariant gate factors (cheap, once per thread)
    const float melt = expf(w_s[hidx]) + 1.0f;
    const float gi   = 1.0f / (1.0f + expf(-w_i[hidx]));
    const float gl   = 1.0f / (1.0f + expf(-w_l[hidx]));

    // softmax over w_o (with max-subtraction to match jax.nn.softmax numerics)
    float wmax = w_o[0];
    #pragma unroll
    for (int i = 1; i < NH; ++i) wmax = fmaxf(wmax, w_o[i]);
    float denom = 0.0f;
    #pragma unroll
    for (int i = 0; i < NH; ++i) denom += expf(w_o[i] - wmax);
    const float a = expf(w_o[hidx] - wmax) / denom;

    float s  = 0.0f;   // snow store
    float hs = 0.0f;   // linear-bucket store

    const float* Pp = P + site;
    const float* Tp = T + site;
    float* Hp = H + gid;
    float* Sp = S + gid;
    float* Qp = Q + site;

    for (int t = 0; t < NT; ++t) {
        const float Pk = Pp[(size_t)t * NS];
        const float Tk = Tp[(size_t)t * NS];

        // SnowBucket
        const float sm = fmaxf(Tk, 0.0f) * melt;     // potential melt
        const float m  = fminf(sm, s);               // actual melt
        s = s - m + ((Tk < 0.0f) ? Pk : 0.0f);       // new snow store
        const float x = ((Tk > 0.0f) ? Pk : 0.0f) + m;

        // input gate + LinearBucket
        const float xin = x * gi;
        const float q   = (xin + hs) * gl;
        hs = hs - q + xin;

        Hp[(size_t)t * (NS * NH)] = hs;
        Sp[(size_t)t * (NS * NH)] = s;

        // Q = sum_h q * a  (16-lane butterfly; xor offsets 1,2,4,8 stay within group)
        float qa = q * a;
        qa += __shfl_xor_sync(0xffffffffu, qa, 1);
        qa += __shfl_xor_sync(0xffffffffu, qa, 2);
        qa += __shfl_xor_sync(0xffffffffu, qa, 4);
        qa += __shfl_xor_sync(0xffffffffu, qa, 8);
        if (hidx == 0) Qp[(size_t)t * NS] = qa;
    }
}

extern "C" void kernel_launch(void* const* d_in, const int* in_sizes, int n_in,
                              void* d_out, int out_size) {
    const float* P   = (const float*)d_in[0];
    const float* T   = (const float*)d_in[1];
    const float* w_i = (const float*)d_in[2];
    const float* w_o = (const float*)d_in[3];
    const float* w_l = (const float*)d_in[4];
    const float* w_s = (const float*)d_in[5];

    float* out = (float*)d_out;
    float* Q = out;                                    // [NT, NS]
    float* H = out + (size_t)NT * NS;                  // [NT, NS, NH]
    float* S = out + (size_t)NT * NS + (size_t)NT * NS * NH;  // [NT, NS, NH]

    const int total = NS * NH;          // 32768 threads
    const int block = 128;
    const int grid  = (total + block - 1) / block;     // 256 blocks
    waternet_kernel<<<grid, block>>>(P, T, w_i, w_o, w_l, w_s, Q, H, S);
}

// round 3
// speedup vs baseline: 2.8215x; 2.8215x over previous
#include <cuda_runtime.h>

#define NT 1096
#define NS 2048
#define NH 16
#define UF 8            // unroll factor; NT = 8 * 137 exactly

__global__ __launch_bounds__(128)
void waternet_kernel(const float* __restrict__ P, const float* __restrict__ T,
                     const float* __restrict__ w_i, const float* __restrict__ w_o,
                     const float* __restrict__ w_l, const float* __restrict__ w_s,
                     float* __restrict__ Q, float* __restrict__ H, float* __restrict__ S)
{
    const int gid  = blockIdx.x * blockDim.x + threadIdx.x;   // site*NH + h
    const int site = gid >> 4;
    const int hidx = gid & 15;

    // Time-invariant gate factors
    const float melt = expf(w_s[hidx]) + 1.0f;
    const float gi   = 1.0f / (1.0f + expf(-w_i[hidx]));
    const float gl   = 1.0f / (1.0f + expf(-w_l[hidx]));

    float wmax = w_o[0];
    #pragma unroll
    for (int i = 1; i < NH; ++i) wmax = fmaxf(wmax, w_o[i]);
    float denom = 0.0f;
    #pragma unroll
    for (int i = 0; i < NH; ++i) denom += expf(w_o[i] - wmax);
    const float a = expf(w_o[hidx] - wmax) / denom;

    float s  = 0.0f;   // snow store
    float hs = 0.0f;   // linear-bucket store

    const float* Pp = P + site;
    const float* Tp = T + site;
    float* Hp = H + gid;
    float* Sp = S + gid;
    float* Qp = Q + site;

    // Double-buffered prefetch: load group g+1 while computing group g.
    float pb[UF], tb[UF];
    #pragma unroll
    for (int i = 0; i < UF; ++i) {
        pb[i] = Pp[(size_t)i * NS];
        tb[i] = Tp[(size_t)i * NS];
    }

    for (int t0 = 0; t0 < NT; t0 += UF) {
        float pc[UF], tc[UF];
        #pragma unroll
        for (int i = 0; i < UF; ++i) { pc[i] = pb[i]; tc[i] = tb[i]; }

        // Prefetch next group (8 independent LDGs issued up front -> MLP=16)
        if (t0 + UF < NT) {
            #pragma unroll
            for (int i = 0; i < UF; ++i) {
                pb[i] = Pp[(size_t)(t0 + UF + i) * NS];
                tb[i] = Tp[(size_t)(t0 + UF + i) * NS];
            }
        }

        float qa[UF];
        #pragma unroll
        for (int i = 0; i < UF; ++i) {
            const float Pk = pc[i];
            const float Tk = tc[i];

            // SnowBucket
            const float sm = fmaxf(Tk, 0.0f) * melt;
            const float m  = fminf(sm, s);
            s = s - m + ((Tk < 0.0f) ? Pk : 0.0f);
            const float x = ((Tk > 0.0f) ? Pk : 0.0f) + m;

            // input gate + LinearBucket
            const float xin = x * gi;
            const float q   = (xin + hs) * gl;
            hs = hs - q + xin;

            const size_t off = (size_t)(t0 + i) * (NS * NH);
            Hp[off] = hs;
            Sp[off] = s;

            qa[i] = q * a;
        }

        // 8 independent 16-lane butterfly reductions; chains interleave.
        #pragma unroll
        for (int i = 0; i < UF; ++i) {
            qa[i] += __shfl_xor_sync(0xffffffffu, qa[i], 1);
            qa[i] += __shfl_xor_sync(0xffffffffu, qa[i], 2);
        }
        #pragma unroll
        for (int i = 0; i < UF; ++i) {
            qa[i] += __shfl_xor_sync(0xffffffffu, qa[i], 4);
            qa[i] += __shfl_xor_sync(0xffffffffu, qa[i], 8);
        }

        if (hidx == 0) {
            #pragma unroll
            for (int i = 0; i < UF; ++i)
                Qp[(size_t)(t0 + i) * NS] = qa[i];
        }
    }
}

extern "C" void kernel_launch(void* const* d_in, const int* in_sizes, int n_in,
                              void* d_out, int out_size) {
    const float* P   = (const float*)d_in[0];
    const float* T   = (const float*)d_in[1];
    const float* w_i = (const float*)d_in[2];
    const float* w_o = (const float*)d_in[3];
    const float* w_l = (const float*)d_in[4];
    const float* w_s = (const float*)d_in[5];

    float* out = (float*)d_out;
    float* Q = out;                                           // [NT, NS]
    float* H = out + (size_t)NT * NS;                         // [NT, NS, NH]
    float* S = out + (size_t)NT * NS + (size_t)NT * NS * NH;  // [NT, NS, NH]

    const int total = NS * NH;          // 32768 threads
    const int block = 128;
    const int grid  = total / block;    // 256 blocks
    waternet_kernel<<<grid, block>>>(P, T, w_i, w_o, w_l, w_s, Q, H, S);
}